// round 1
// baseline (speedup 1.0000x reference)
#include <cuda_runtime.h>
#include <cuda_bf16.h>
#include <cstdint>

// Problem constants
#define BN   4096           // B*N = 8*512
#define HDIM 128            // H
#define MDIM 128            // M (stack depth)
#define EDIM 128            // E
#define ODIM 128            // O

// Output buffer layout (concatenated, float32):
//   out     : BN*ODIM            @ 0
//   new_mem : BN*MDIM*EDIM       @ MEM_OFF
//   new_rs  : BN*MDIM            @ RS_OFF
//   new_wm  : BN*MDIM            @ WM_OFF
#define MEM_OFF ((size_t)BN * ODIM)                       // 524288
#define RS_OFF  (MEM_OFF + (size_t)BN * MDIM * EDIM)      // 67633152
#define WM_OFF  (RS_OFF + (size_t)BN * MDIM)              // 68157440

__global__ __launch_bounds__(128, 8)
void mlp_stack_memory_fused(
    const float* __restrict__ nxt_hidden,     // (BN, H)
    const float* __restrict__ memory_values,  // (BN, M, E)
    const float* __restrict__ read_strengths, // (BN, M)  [flattened (BN,1,M,1)]
    const float* __restrict__ write_mask,     // (BN, M)
    const float* __restrict__ w_push,         // (H,)
    const float* __restrict__ b_push,         // (1,)
    const float* __restrict__ w_pop,          // (H,)
    const float* __restrict__ b_pop,          // (1,)
    const float* __restrict__ w_val,          // (H, E) row-major
    const float* __restrict__ b_val,          // (E,)
    const float* __restrict__ w_out,          // (E, O) row-major
    const float* __restrict__ b_out,          // (O,)
    float* __restrict__ out)                  // concatenated output
{
    const int bn = blockIdx.x;
    const int t  = threadIdx.x;     // 0..127

    __shared__ float sh_h[HDIM];
    __shared__ float sh_s[MDIM];
    __shared__ float sh_w[MDIM];
    __shared__ float sh_vals[EDIM];
    __shared__ float sh_snew[MDIM];
    __shared__ float sh_coeff[MDIM];
    __shared__ float sh_acc[4][EDIM];
    __shared__ float sh_rv[EDIM];

    // ---- stage 1: load per-row small vectors ----
    sh_h[t] = nxt_hidden[(size_t)bn * HDIM + t];
    sh_s[t] = read_strengths[(size_t)bn * MDIM + t];
    sh_w[t] = write_mask[(size_t)bn * MDIM + t];
    __syncthreads();

    // ---- push / pop gates (redundant per-thread dot; 128 FMAs, L2-resident weights) ----
    float ap = 0.f, aq = 0.f;
    #pragma unroll 8
    for (int k = 0; k < HDIM; k++) {
        float hk = sh_h[k];
        ap += hk * __ldg(&w_push[k]);
        aq += hk * __ldg(&w_pop[k]);
    }
    const float push = 1.f / (1.f + expf(-(ap + __ldg(&b_push[0]))));
    const float pop  = 1.f / (1.f + expf(-(aq + __ldg(&b_pop[0]))));

    // ---- vals[e=t] = tanh(h . w_val[:,t] + b_val[t]) ----
    float vacc = __ldg(&b_val[t]);
    #pragma unroll 8
    for (int k = 0; k < HDIM; k++)
        vacc += sh_h[k] * __ldg(&w_val[k * EDIM + t]);
    sh_vals[t] = tanhf(vacc);

    // ---- stack-strength update (suffix sums, thread m = t) ----
    float sa1 = 0.f;
    for (int j = t + 1; j < MDIM; j++) sa1 += sh_s[j];
    const float s_m   = sh_s[t];
    const float s_pop = fmaxf(s_m - fmaxf(pop - sa1, 0.f), 0.f);
    const float s_new = s_pop + push * sh_w[t];
    sh_snew[t] = s_new;
    __syncthreads();

    float sa2 = 0.f;
    for (int j = t + 1; j < MDIM; j++) sa2 += sh_snew[j];
    sh_coeff[t] = fminf(s_new, fmaxf(1.f - sa2, 0.f));
    __syncthreads();

    // ---- stage 2: stream the 128x128 memory tile once (float4, 4 rows x 32 cols) ----
    const int r = t >> 5;        // row-in-group 0..3
    const int c = t & 31;        // vec4 column 0..31
    const float4* __restrict__ mem4 =
        (const float4*)(memory_values + (size_t)bn * MDIM * EDIM);
    float4* __restrict__ nm4 =
        (float4*)(out + MEM_OFF + (size_t)bn * MDIM * EDIM);
    const float4 v4 = ((const float4*)sh_vals)[c];

    float4 acc = make_float4(0.f, 0.f, 0.f, 0.f);
    #pragma unroll 4
    for (int mb = 0; mb < MDIM / 4; mb++) {
        const int m = mb * 4 + r;
        float4 x = mem4[m * 32 + c];
        const float wm = sh_w[m];
        const float cm = sh_coeff[m];
        x.x += wm * v4.x;  x.y += wm * v4.y;
        x.z += wm * v4.z;  x.w += wm * v4.w;
        nm4[m * 32 + c] = x;
        acc.x += cm * x.x;  acc.y += cm * x.y;
        acc.z += cm * x.z;  acc.w += cm * x.w;
    }

    // ---- reduce read_vals across the 4 row-groups ----
    ((float4*)sh_acc[r])[c] = acc;
    __syncthreads();
    sh_rv[t] = sh_acc[0][t] + sh_acc[1][t] + sh_acc[2][t] + sh_acc[3][t];
    __syncthreads();

    // ---- out[o=t] = read_vals . w_out[:,t] + b_out[t] ----
    float oacc = __ldg(&b_out[t]);
    #pragma unroll 8
    for (int k = 0; k < EDIM; k++)
        oacc += sh_rv[k] * __ldg(&w_out[k * ODIM + t]);

    out[(size_t)bn * ODIM + t]        = oacc;
    out[RS_OFF + (size_t)bn * MDIM + t] = s_new;
    out[WM_OFF + (size_t)bn * MDIM + t] = sh_w[(t + MDIM - 1) & (MDIM - 1)];
}

extern "C" void kernel_launch(void* const* d_in, const int* in_sizes, int n_in,
                              void* d_out, int out_size) {
    const float* nxt_hidden     = (const float*)d_in[0];
    const float* memory_values  = (const float*)d_in[1];
    const float* read_strengths = (const float*)d_in[2];
    const float* write_mask     = (const float*)d_in[3];
    const float* w_push         = (const float*)d_in[4];
    const float* b_push         = (const float*)d_in[5];
    const float* w_pop          = (const float*)d_in[6];
    const float* b_pop          = (const float*)d_in[7];
    const float* w_val          = (const float*)d_in[8];
    const float* b_val          = (const float*)d_in[9];
    const float* w_out          = (const float*)d_in[10];
    const float* b_out          = (const float*)d_in[11];
    float* out = (float*)d_out;

    mlp_stack_memory_fused<<<BN, 128>>>(
        nxt_hidden, memory_values, read_strengths, write_mask,
        w_push, b_push, w_pop, b_pop, w_val, b_val, w_out, b_out, out);
}

// round 11
// speedup vs baseline: 1.0862x; 1.0862x over previous
#include <cuda_runtime.h>
#include <cuda_bf16.h>
#include <cstdint>

#define BN   4096
#define HDIM 128
#define MDIM 128
#define EDIM 128
#define ODIM 128

// Persistent streamer grid: 148 SMs x 12 CTAs/SM
#define STREAM_GRID (148 * 12)

// Output layout (concatenated float32)
#define MEM_OFF ((size_t)BN * ODIM)
#define RS_OFF  (MEM_OFF + (size_t)BN * MDIM * EDIM)
#define WM_OFF  (RS_OFF + (size_t)BN * MDIM)

// Scratch (device globals — no runtime allocation)
__device__ float g_coeff[BN * MDIM];
__device__ float g_vals [BN * EDIM];

// ============================================================================
// Kernel 1: gates / vals / stack-strength math (small traffic, ~5-8 us)
// ============================================================================
__global__ __launch_bounds__(128, 8)
void gates_kernel(
    const float* __restrict__ nxt_hidden,
    const float* __restrict__ read_strengths,
    const float* __restrict__ write_mask,
    const float* __restrict__ w_push, const float* __restrict__ b_push,
    const float* __restrict__ w_pop,  const float* __restrict__ b_pop,
    const float* __restrict__ w_val,  const float* __restrict__ b_val,
    float* __restrict__ out)
{
    const int bn = blockIdx.x;
    const int t  = threadIdx.x;

    __shared__ float sh_h[HDIM];
    __shared__ float sh_s[MDIM];
    __shared__ float sh_w[MDIM];
    __shared__ float sh_snew[MDIM];

    sh_h[t] = nxt_hidden[(size_t)bn * HDIM + t];
    sh_s[t] = read_strengths[(size_t)bn * MDIM + t];
    sh_w[t] = write_mask[(size_t)bn * MDIM + t];
    __syncthreads();

    // push / pop gates (redundant per-thread dot, weights L2-resident)
    float ap = 0.f, aq = 0.f;
    #pragma unroll 8
    for (int k = 0; k < HDIM; k++) {
        float hk = sh_h[k];
        ap += hk * __ldg(&w_push[k]);
        aq += hk * __ldg(&w_pop[k]);
    }
    const float push = 1.f / (1.f + expf(-(ap + __ldg(&b_push[0]))));
    const float pop  = 1.f / (1.f + expf(-(aq + __ldg(&b_pop[0]))));

    // vals[e=t] = tanh(h . w_val[:,t] + b_val[t])
    float vacc = __ldg(&b_val[t]);
    #pragma unroll 8
    for (int k = 0; k < HDIM; k++)
        vacc += sh_h[k] * __ldg(&w_val[k * EDIM + t]);
    g_vals[(size_t)bn * EDIM + t] = tanhf(vacc);

    // stack-strength update (suffix sums)
    float sa1 = 0.f;
    #pragma unroll 8
    for (int j = t + 1; j < MDIM; j++) sa1 += sh_s[j];
    const float s_pop = fmaxf(sh_s[t] - fmaxf(pop - sa1, 0.f), 0.f);
    const float s_new = s_pop + push * sh_w[t];
    sh_snew[t] = s_new;
    __syncthreads();

    float sa2 = 0.f;
    #pragma unroll 8
    for (int j = t + 1; j < MDIM; j++) sa2 += sh_snew[j];
    g_coeff[(size_t)bn * MDIM + t] = fminf(s_new, fmaxf(1.f - sa2, 0.f));

    // small outputs
    out[RS_OFF + (size_t)bn * MDIM + t] = s_new;
    out[WM_OFF + (size_t)bn * MDIM + t] = sh_w[(t + MDIM - 1) & (MDIM - 1)];
}

// ============================================================================
// Kernel 2: persistent grid-stride streamer + read_vals + out matvec
// ============================================================================
__global__ __launch_bounds__(128, 12)
void stream_kernel(
    const float* __restrict__ memory_values,
    const float* __restrict__ write_mask,
    const float* __restrict__ w_out, const float* __restrict__ b_out,
    float* __restrict__ out)
{
    const int t = threadIdx.x;
    const int r = t >> 5;        // row-in-group 0..3
    const int c = t & 31;        // vec4 column 0..31

    __shared__ float sh_w[MDIM];
    __shared__ float sh_coeff[MDIM];
    __shared__ float sh_vals[EDIM];
    __shared__ float sh_acc[4][EDIM];
    __shared__ float sh_rv[EDIM];

    for (int bn = blockIdx.x; bn < BN; bn += STREAM_GRID) {
        __syncthreads();   // shared buffers free from previous row
        sh_w[t]     = write_mask[(size_t)bn * MDIM + t];
        sh_coeff[t] = g_coeff[(size_t)bn * MDIM + t];
        sh_vals[t]  = g_vals[(size_t)bn * EDIM + t];
        __syncthreads();

        const float4* __restrict__ mem4 =
            (const float4*)(memory_values + (size_t)bn * MDIM * EDIM);
        float4* __restrict__ nm4 =
            (float4*)(out + MEM_OFF + (size_t)bn * MDIM * EDIM);
        const float4 v4 = ((const float4*)sh_vals)[c];

        float4 acc = make_float4(0.f, 0.f, 0.f, 0.f);
        // 32 m-rows per thread, batches of 4 with front-batched loads
        #pragma unroll
        for (int mb = 0; mb < 8; mb++) {
            float4 x[4];
            #pragma unroll
            for (int i = 0; i < 4; i++)
                x[i] = __ldcs(&mem4[(mb * 16 + i * 4 + r) * 32 + c]);
            #pragma unroll
            for (int i = 0; i < 4; i++) {
                const int m = mb * 16 + i * 4 + r;
                const float wm = sh_w[m];
                const float cm = sh_coeff[m];
                x[i].x += wm * v4.x;  x[i].y += wm * v4.y;
                x[i].z += wm * v4.z;  x[i].w += wm * v4.w;
                __stcs(&nm4[m * 32 + c], x[i]);   // write-once data
                acc.x += cm * x[i].x;  acc.y += cm * x[i].y;
                acc.z += cm * x[i].z;  acc.w += cm * x[i].w;
            }
        }

        // reduce read_vals across the 4 row-groups
        ((float4*)sh_acc[r])[c] = acc;
        __syncthreads();
        sh_rv[t] = sh_acc[0][t] + sh_acc[1][t] + sh_acc[2][t] + sh_acc[3][t];
        __syncthreads();

        // out[o=t] = read_vals . w_out[:,t] + b_out[t]
        float oacc = __ldg(&b_out[t]);
        #pragma unroll 8
        for (int k = 0; k < EDIM; k++)
            oacc += sh_rv[k] * __ldg(&w_out[k * ODIM + t]);
        out[(size_t)bn * ODIM + t] = oacc;
    }
}

extern "C" void kernel_launch(void* const* d_in, const int* in_sizes, int n_in,
                              void* d_out, int out_size) {
    const float* nxt_hidden     = (const float*)d_in[0];
    const float* memory_values  = (const float*)d_in[1];
    const float* read_strengths = (const float*)d_in[2];
    const float* write_mask     = (const float*)d_in[3];
    const float* w_push         = (const float*)d_in[4];
    const float* b_push         = (const float*)d_in[5];
    const float* w_pop          = (const float*)d_in[6];
    const float* b_pop          = (const float*)d_in[7];
    const float* w_val          = (const float*)d_in[8];
    const float* b_val          = (const float*)d_in[9];
    const float* w_out          = (const float*)d_in[10];
    const float* b_out          = (const float*)d_in[11];
    float* out = (float*)d_out;

    gates_kernel<<<BN, 128>>>(nxt_hidden, read_strengths, write_mask,
                              w_push, b_push, w_pop, b_pop, w_val, b_val, out);
    stream_kernel<<<STREAM_GRID, 128>>>(memory_values, write_mask,
                                        w_out, b_out, out);
}